// round 3
// baseline (speedup 1.0000x reference)
#include <cuda_runtime.h>
#include <cuda_bf16.h>

#define MAXN 65536
#define MAXE 1048576
#define MAXET (MAXE + MAXN)
#define F_IN 128
#define HC 256     // HEADS*HID
#define HID 64
#define HEADS 4

// ---------------- scratch (static device globals; no allocs allowed) ----------
__device__ float    g_xs[(size_t)MAXN * HC];      // 64 MB
__device__ float    g_xd[(size_t)MAXN * HC];      // 64 MB
__device__ float    g_logits[(size_t)MAXET * HEADS]; // logits, then p in-place
__device__ unsigned g_segmax[(size_t)MAXN * HEADS];
__device__ float    g_segsum[(size_t)MAXN * HEADS];
__device__ float    g_accum[(size_t)MAXN * HID];  // 16 MB
__device__ float    g_stats[4 * F_IN];            // [sum | sumsq | scale | shift]

// ---------------- helpers ----------------------------------------------------
// Order-preserving float->uint encoding. Every real float maps to a value > 0,
// so memset(0) is a valid identity for atomicMax.
__device__ __forceinline__ unsigned fenc(float f) {
    unsigned u = __float_as_uint(f);
    return (u & 0x80000000u) ? ~u : (u | 0x80000000u);
}
__device__ __forceinline__ float fdec(unsigned u) {
    return (u & 0x80000000u) ? __uint_as_float(u ^ 0x80000000u) : __uint_as_float(~u);
}
// branch-free leaky relu: FMNMX + FFMA
__device__ __forceinline__ float lrelu(float v) {
    return fmaxf(v, 0.f) + 0.2f * fminf(v, 0.f);
}

// ---------------- K1: BN stats (sum, sumsq per column) ------------------------
__global__ void bn_stats(const float* __restrict__ x, int N) {
    __shared__ float shs[256], shq[256];
    int col  = threadIdx.x & 127;
    int half = threadIdx.x >> 7;
    float s = 0.f, q = 0.f;
    for (int r = blockIdx.x * 2 + half; r < N; r += gridDim.x * 2) {
        float v = x[(size_t)r * F_IN + col];
        s += v; q += v * v;
    }
    shs[threadIdx.x] = s; shq[threadIdx.x] = q;
    __syncthreads();
    if (half == 0) {
        atomicAdd(&g_stats[col],        s + shs[threadIdx.x + 128]);
        atomicAdd(&g_stats[F_IN + col], q + shq[threadIdx.x + 128]);
    }
}

// ---------------- K1b: finalize scale/shift ----------------------------------
__global__ void bn_final(const float* __restrict__ gamma, const float* __restrict__ beta, int N) {
    int c = threadIdx.x;
    if (c >= F_IN) return;
    float inv_n = 1.f / (float)N;
    float mean = g_stats[c] * inv_n;
    float var  = g_stats[F_IN + c] * inv_n - mean * mean;
    float sc   = gamma[c] * rsqrtf(var + 1e-5f);
    g_stats[2 * F_IN + c] = sc;
    g_stats[3 * F_IN + c] = beta[c] - mean * sc;
}

// ---------------- K2: fused BN-normalize + dual GEMM -------------------------
// xs = xn @ w_l^T + b_l ; xd = xn @ w_r^T + b_r as one GEMM with 512 output
// cols. Block tile 128x128, K-chunks of 32, 8x8 per-thread micro-tile.
__global__ __launch_bounds__(256) void gemm_xsxd(
    const float* __restrict__ x,
    const float* __restrict__ wl, const float* __restrict__ bl,
    const float* __restrict__ wr, const float* __restrict__ br, int N)
{
    __shared__ float As[32][132];
    __shared__ float Bs[32][132];
    __shared__ float sc[F_IN], sf[F_IN];

    int tid  = threadIdx.x;
    int row0 = blockIdx.y * 128;
    int col0 = blockIdx.x * 128;   // in [0,512)

    if (tid < F_IN) {
        sc[tid] = g_stats[2 * F_IN + tid];
        sf[tid] = g_stats[3 * F_IN + tid];
    }
    __syncthreads();

    float acc[8][8];
#pragma unroll
    for (int i = 0; i < 8; i++)
#pragma unroll
        for (int j = 0; j < 8; j++) acc[i][j] = 0.f;

    int ty = tid >> 4, tx = tid & 15;

    for (int k0 = 0; k0 < F_IN; k0 += 32) {
        // load A (BN applied on the fly): 128 rows x 32 k
#pragma unroll
        for (int t = 0; t < 4; t++) {
            int L = tid + t * 256;      // 0..1023 float4 tasks
            int r = L >> 3;
            int kq = L & 7;
            int gr = row0 + r;
            float4 v = *(const float4*)&x[(size_t)gr * F_IN + k0 + kq * 4];
            int kk = kq * 4;
            As[kk + 0][r] = v.x * sc[k0 + kk + 0] + sf[k0 + kk + 0];
            As[kk + 1][r] = v.y * sc[k0 + kk + 1] + sf[k0 + kk + 1];
            As[kk + 2][r] = v.z * sc[k0 + kk + 2] + sf[k0 + kk + 2];
            As[kk + 3][r] = v.w * sc[k0 + kk + 3] + sf[k0 + kk + 3];
        }
        // load B: Bs[k][col] = W[globalcol][k]
#pragma unroll
        for (int t = 0; t < 4; t++) {
            int L = tid + t * 256;
            int c = L >> 3;
            int kq = L & 7;
            int gc = col0 + c;
            const float* wsrc = (gc < HC) ? &wl[(size_t)gc * F_IN]
                                          : &wr[(size_t)(gc - HC) * F_IN];
            float4 v = *(const float4*)&wsrc[k0 + kq * 4];
            int kk = kq * 4;
            Bs[kk + 0][c] = v.x; Bs[kk + 1][c] = v.y;
            Bs[kk + 2][c] = v.z; Bs[kk + 3][c] = v.w;
        }
        __syncthreads();
#pragma unroll
        for (int k = 0; k < 32; k++) {
            float a[8], b[8];
            *(float4*)(a)     = *(const float4*)&As[k][ty * 8];
            *(float4*)(a + 4) = *(const float4*)&As[k][ty * 8 + 4];
            *(float4*)(b)     = *(const float4*)&Bs[k][tx * 8];
            *(float4*)(b + 4) = *(const float4*)&Bs[k][tx * 8 + 4];
#pragma unroll
            for (int i = 0; i < 8; i++)
#pragma unroll
                for (int j = 0; j < 8; j++) acc[i][j] += a[i] * b[j];
        }
        __syncthreads();
    }

    // epilogue: add bias, route to g_xs / g_xd (whole block is one side)
    bool is_l = (col0 < HC);
    float bias8[8];
#pragma unroll
    for (int j = 0; j < 8; j++) {
        int gc = col0 + tx * 8 + j;
        bias8[j] = is_l ? bl[gc] : br[gc - HC];
    }
#pragma unroll
    for (int i = 0; i < 8; i++) {
        int gr = row0 + ty * 8 + i;
        int gc = col0 + tx * 8;
        float* dstp = is_l ? &g_xs[(size_t)gr * HC + gc]
                           : &g_xd[(size_t)gr * HC + (gc - HC)];
        float4 v0, v1;
        v0.x = acc[i][0] + bias8[0]; v0.y = acc[i][1] + bias8[1];
        v0.z = acc[i][2] + bias8[2]; v0.w = acc[i][3] + bias8[3];
        v1.x = acc[i][4] + bias8[4]; v1.y = acc[i][5] + bias8[5];
        v1.z = acc[i][6] + bias8[6]; v1.w = acc[i][7] + bias8[7];
        *(float4*)(dstp)     = v0;
        *(float4*)(dstp + 4) = v1;
    }
}

// ---------------- K3: per-edge attention logits + segment max ----------------
// one warp per edge; lane l covers head l>>3, channels (l&7)*8 .. +7
__global__ void edge_logits(const int* __restrict__ ei, const float* __restrict__ att,
                            int E, int Et)
{
    int gwarp = (blockIdx.x * blockDim.x + threadIdx.x) >> 5;
    int lane  = threadIdx.x & 31;
    if (gwarp >= Et) return;
    int src, dst;
    if (gwarp < E) { src = __ldg(&ei[gwarp]); dst = __ldg(&ei[E + gwarp]); }
    else           { src = dst = gwarp - E; }

    const float4* ps = (const float4*)&g_xs[(size_t)src * HC + lane * 8];
    const float4* pd = (const float4*)&g_xd[(size_t)dst * HC + lane * 8];
    float4 s0 = ps[0], s1 = ps[1];
    float4 d0 = pd[0], d1 = pd[1];
    float4 a0 = *(const float4*)&att[lane * 8];
    float4 a1 = *(const float4*)&att[lane * 8 + 4];

    float acc = lrelu(s0.x + d0.x) * a0.x + lrelu(s0.y + d0.y) * a0.y
              + lrelu(s0.z + d0.z) * a0.z + lrelu(s0.w + d0.w) * a0.w
              + lrelu(s1.x + d1.x) * a1.x + lrelu(s1.y + d1.y) * a1.y
              + lrelu(s1.z + d1.z) * a1.z + lrelu(s1.w + d1.w) * a1.w;
#pragma unroll
    for (int off = 4; off >= 1; off >>= 1)
        acc += __shfl_xor_sync(0xFFFFFFFFu, acc, off);
    if ((lane & 7) == 0) {
        int h = lane >> 3;
        g_logits[(size_t)gwarp * HEADS + h] = acc;
        atomicMax(&g_segmax[(size_t)dst * HEADS + h], fenc(acc));
    }
}

// ---------------- K4: p = exp(logit - segmax); vector segment sum ------------
// one thread per edge: float4 logits, 4 exps, one red.v4 into segsum[dst]
__global__ void edge_softmax_p(const int* __restrict__ ei, int E, int Et) {
    int e = blockIdx.x * blockDim.x + threadIdx.x;
    if (e >= Et) return;
    int dst = (e < E) ? __ldg(&ei[E + e]) : (e - E);
    float4 lg = *(const float4*)&g_logits[(size_t)e * HEADS];
    const unsigned* mp = &g_segmax[(size_t)dst * HEADS];
    float4 p;
    p.x = __expf(lg.x - fdec(mp[0]));
    p.y = __expf(lg.y - fdec(mp[1]));
    p.z = __expf(lg.z - fdec(mp[2]));
    p.w = __expf(lg.w - fdec(mp[3]));
    *(float4*)&g_logits[(size_t)e * HEADS] = p;
    float* sp = &g_segsum[(size_t)dst * HEADS];
    asm volatile("red.global.add.v4.f32 [%0], {%1,%2,%3,%4};"
                 :: "l"(sp), "f"(p.x), "f"(p.y), "f"(p.z), "f"(p.w)
                 : "memory");
}

// ---------------- K5: aggregate alpha-weighted messages ----------------------
// half-warp per edge; subgroup lane sl in [0,16) covers channels sl*4..sl*4+3;
// mean over heads folded in (0.25 * sum_h alpha_h * xs[src][h][c]).
__global__ void aggregate(const int* __restrict__ ei, int E, int Et) {
    int e    = (blockIdx.x * blockDim.x + threadIdx.x) >> 4;
    int lane = threadIdx.x & 31;
    int sl   = lane & 15;
    if (e >= Et) return;
    int src, dst;
    if (e < E) { src = __ldg(&ei[e]); dst = __ldg(&ei[E + e]); }
    else       { src = dst = e - E; }

    float pv = 0.f;
    if (sl < 4)
        pv = g_logits[(size_t)e * HEADS + sl] / g_segsum[(size_t)dst * HEADS + sl];
    float a[4];
#pragma unroll
    for (int h = 0; h < 4; h++)
        a[h] = __shfl_sync(0xFFFFFFFFu, pv, (lane & 16) + h);

    float4 acc = make_float4(0.f, 0.f, 0.f, 0.f);
#pragma unroll
    for (int h = 0; h < 4; h++) {
        float4 v = *(const float4*)&g_xs[(size_t)src * HC + h * HID + sl * 4];
        acc.x += a[h] * v.x; acc.y += a[h] * v.y;
        acc.z += a[h] * v.z; acc.w += a[h] * v.w;
    }
    acc.x *= 0.25f; acc.y *= 0.25f; acc.z *= 0.25f; acc.w *= 0.25f;
    float* pa = &g_accum[(size_t)dst * HID + sl * 4];
    asm volatile("red.global.add.v4.f32 [%0], {%1,%2,%3,%4};"
                 :: "l"(pa), "f"(acc.x), "f"(acc.y), "f"(acc.z), "f"(acc.w)
                 : "memory");
}

// ---------------- K6: bias + ELU ---------------------------------------------
__global__ void finalize(const float* __restrict__ bias, float* __restrict__ out, int total) {
    int i = blockIdx.x * blockDim.x + threadIdx.x;
    if (i >= total) return;
    float v = g_accum[i] + bias[i & (HID - 1)];
    out[i] = v > 0.f ? v : expm1f(v);
}

// ---------------- launch ------------------------------------------------------
extern "C" void kernel_launch(void* const* d_in, const int* in_sizes, int n_in,
                              void* d_out, int out_size)
{
    const float* x  = (const float*)d_in[0];
    const int*   ei = (const int*)d_in[1];
    // d_in[2] = batch (unused). num_graphs may or may not appear as a tensor.
    int wi = 3;
    if (n_in >= 12 && in_sizes[3] == 1) wi = 4;  // skip scalar num_graphs
    const float* gamma = (const float*)d_in[wi + 0];
    const float* beta  = (const float*)d_in[wi + 1];
    const float* wl    = (const float*)d_in[wi + 2];
    const float* bl    = (const float*)d_in[wi + 3];
    const float* wr    = (const float*)d_in[wi + 4];
    const float* br    = (const float*)d_in[wi + 5];
    const float* att   = (const float*)d_in[wi + 6];
    const float* bias  = (const float*)d_in[wi + 7];

    int N  = in_sizes[0] / F_IN;
    int E  = in_sizes[1] / 2;
    int Et = E + N;

    void *p_stats, *p_segmax, *p_segsum, *p_accum;
    cudaGetSymbolAddress(&p_stats,  g_stats);
    cudaGetSymbolAddress(&p_segmax, g_segmax);
    cudaGetSymbolAddress(&p_segsum, g_segsum);
    cudaGetSymbolAddress(&p_accum,  g_accum);
    cudaMemsetAsync(p_stats,  0, (size_t)2 * F_IN * sizeof(float));
    cudaMemsetAsync(p_segmax, 0, (size_t)N * HEADS * sizeof(unsigned));
    cudaMemsetAsync(p_segsum, 0, (size_t)N * HEADS * sizeof(float));
    cudaMemsetAsync(p_accum,  0, (size_t)N * HID * sizeof(float));

    bn_stats<<<256, 256>>>(x, N);
    bn_final<<<1, 128>>>(gamma, beta, N);

    dim3 g2(4, (N + 127) / 128);
    gemm_xsxd<<<g2, 256>>>(x, wl, bl, wr, br, N);

    int tE = Et * 32;
    edge_logits<<<(tE + 255) / 256, 256>>>(ei, att, E, Et);

    edge_softmax_p<<<(Et + 255) / 256, 256>>>(ei, E, Et);

    int tA = Et * 16;
    aggregate<<<(tA + 255) / 256, 256>>>(ei, E, Et);

    int tF = N * HID;
    finalize<<<(tF + 255) / 256, 256>>>(bias, (float*)d_out, tF);
}

// round 7
// speedup vs baseline: 1.4067x; 1.4067x over previous
#include <cuda_runtime.h>
#include <cuda_bf16.h>

#define MAXN 65536
#define MAXE 1048576
#define MAXET (MAXE + MAXN)
#define F_IN 128
#define HC 256     // HEADS*HID
#define HID 64
#define HEADS 4

// ---------------- scratch ------------------------------------------------------
__device__ float g_xs[(size_t)MAXN * HC];      // 64 MB
__device__ float g_xd[(size_t)MAXN * HC];      // 64 MB
__device__ int   g_cnt[MAXN];
__device__ int   g_fill[MAXN];
__device__ int   g_rowptr[MAXN + 1];
__device__ int   g_col[MAXET];
__device__ int   g_part[256];
__device__ float g_stats[4 * F_IN];            // [sum | sumsq | scale | shift]

__device__ __forceinline__ float lrelu(float v) {
    return fmaxf(v, 0.f) + 0.2f * fminf(v, 0.f);
}

// ---------------- K1: BN stats -------------------------------------------------
__global__ void bn_stats(const float* __restrict__ x, int N) {
    __shared__ float shs[256], shq[256];
    int col  = threadIdx.x & 127;
    int half = threadIdx.x >> 7;
    float s = 0.f, q = 0.f;
    for (int r = blockIdx.x * 2 + half; r < N; r += gridDim.x * 2) {
        float v = x[(size_t)r * F_IN + col];
        s += v; q += v * v;
    }
    shs[threadIdx.x] = s; shq[threadIdx.x] = q;
    __syncthreads();
    if (half == 0) {
        atomicAdd(&g_stats[col],        s + shs[threadIdx.x + 128]);
        atomicAdd(&g_stats[F_IN + col], q + shq[threadIdx.x + 128]);
    }
}

__global__ void bn_final(const float* __restrict__ gamma, const float* __restrict__ beta, int N) {
    int c = threadIdx.x;
    if (c >= F_IN) return;
    float inv_n = 1.f / (float)N;
    float mean = g_stats[c] * inv_n;
    float var  = g_stats[F_IN + c] * inv_n - mean * mean;
    float sc   = gamma[c] * rsqrtf(var + 1e-5f);
    g_stats[2 * F_IN + c] = sc;
    g_stats[3 * F_IN + c] = beta[c] - mean * sc;
}

// ---------------- K2: fused BN-normalize + dual GEMM ---------------------------
__global__ __launch_bounds__(256) void gemm_xsxd(
    const float* __restrict__ x,
    const float* __restrict__ wl, const float* __restrict__ bl,
    const float* __restrict__ wr, const float* __restrict__ br, int N)
{
    __shared__ float As[32][132];
    __shared__ float Bs[32][132];
    __shared__ float sc[F_IN], sf[F_IN];

    int tid  = threadIdx.x;
    int row0 = blockIdx.y * 128;
    int col0 = blockIdx.x * 128;

    if (tid < F_IN) {
        sc[tid] = g_stats[2 * F_IN + tid];
        sf[tid] = g_stats[3 * F_IN + tid];
    }
    __syncthreads();

    float acc[8][8];
#pragma unroll
    for (int i = 0; i < 8; i++)
#pragma unroll
        for (int j = 0; j < 8; j++) acc[i][j] = 0.f;

    int ty = tid >> 4, tx = tid & 15;

    for (int k0 = 0; k0 < F_IN; k0 += 32) {
#pragma unroll
        for (int t = 0; t < 4; t++) {
            int L = tid + t * 256;
            int r = L >> 3;
            int kq = L & 7;
            int gr = row0 + r;
            float4 v = *(const float4*)&x[(size_t)gr * F_IN + k0 + kq * 4];
            int kk = kq * 4;
            As[kk + 0][r] = v.x * sc[k0 + kk + 0] + sf[k0 + kk + 0];
            As[kk + 1][r] = v.y * sc[k0 + kk + 1] + sf[k0 + kk + 1];
            As[kk + 2][r] = v.z * sc[k0 + kk + 2] + sf[k0 + kk + 2];
            As[kk + 3][r] = v.w * sc[k0 + kk + 3] + sf[k0 + kk + 3];
        }
#pragma unroll
        for (int t = 0; t < 4; t++) {
            int L = tid + t * 256;
            int c = L >> 3;
            int kq = L & 7;
            int gc = col0 + c;
            const float* wsrc = (gc < HC) ? &wl[(size_t)gc * F_IN]
                                          : &wr[(size_t)(gc - HC) * F_IN];
            float4 v = *(const float4*)&wsrc[k0 + kq * 4];
            int kk = kq * 4;
            Bs[kk + 0][c] = v.x; Bs[kk + 1][c] = v.y;
            Bs[kk + 2][c] = v.z; Bs[kk + 3][c] = v.w;
        }
        __syncthreads();
#pragma unroll
        for (int k = 0; k < 32; k++) {
            float a[8], b[8];
            *(float4*)(a)     = *(const float4*)&As[k][ty * 8];
            *(float4*)(a + 4) = *(const float4*)&As[k][ty * 8 + 4];
            *(float4*)(b)     = *(const float4*)&Bs[k][tx * 8];
            *(float4*)(b + 4) = *(const float4*)&Bs[k][tx * 8 + 4];
#pragma unroll
            for (int i = 0; i < 8; i++)
#pragma unroll
                for (int j = 0; j < 8; j++) acc[i][j] += a[i] * b[j];
        }
        __syncthreads();
    }

    bool is_l = (col0 < HC);
    float bias8[8];
#pragma unroll
    for (int j = 0; j < 8; j++) {
        int gc = col0 + tx * 8 + j;
        bias8[j] = is_l ? bl[gc] : br[gc - HC];
    }
#pragma unroll
    for (int i = 0; i < 8; i++) {
        int gr = row0 + ty * 8 + i;
        int gc = col0 + tx * 8;
        float* dstp = is_l ? &g_xs[(size_t)gr * HC + gc]
                           : &g_xd[(size_t)gr * HC + (gc - HC)];
        float4 v0, v1;
        v0.x = acc[i][0] + bias8[0]; v0.y = acc[i][1] + bias8[1];
        v0.z = acc[i][2] + bias8[2]; v0.w = acc[i][3] + bias8[3];
        v1.x = acc[i][4] + bias8[4]; v1.y = acc[i][5] + bias8[5];
        v1.z = acc[i][6] + bias8[6]; v1.w = acc[i][7] + bias8[7];
        *(float4*)(dstp)     = v0;
        *(float4*)(dstp + 4) = v1;
    }
}

// ---------------- CSR build ----------------------------------------------------
__global__ void csr_hist(const int* __restrict__ ei, int E) {
    int e = blockIdx.x * blockDim.x + threadIdx.x;
    if (e < E) atomicAdd(&g_cnt[__ldg(&ei[E + e])], 1);
}

__global__ void csr_scan1(int N) {
    __shared__ int sm[256];
    int t = blockIdx.x * 256 + threadIdx.x;
    sm[threadIdx.x] = (t < N) ? (g_cnt[t] + 1) : 0;
    __syncthreads();
#pragma unroll
    for (int off = 128; off > 0; off >>= 1) {
        if (threadIdx.x < off) sm[threadIdx.x] += sm[threadIdx.x + off];
        __syncthreads();
    }
    if (threadIdx.x == 0) g_part[blockIdx.x] = sm[0];
}

__global__ void csr_scan2() {
    __shared__ int sm[256];
    int v = g_part[threadIdx.x];
    sm[threadIdx.x] = v;
    __syncthreads();
    for (int off = 1; off < 256; off <<= 1) {
        int a = (threadIdx.x >= off) ? sm[threadIdx.x - off] : 0;
        __syncthreads();
        sm[threadIdx.x] += a;
        __syncthreads();
    }
    g_part[threadIdx.x] = sm[threadIdx.x] - v;   // exclusive
}

__global__ void csr_scan3(int N) {
    __shared__ int sm[256];
    int t = blockIdx.x * 256 + threadIdx.x;
    int v = (t < N) ? (g_cnt[t] + 1) : 0;
    sm[threadIdx.x] = v;
    __syncthreads();
    for (int off = 1; off < 256; off <<= 1) {
        int a = (threadIdx.x >= off) ? sm[threadIdx.x - off] : 0;
        __syncthreads();
        sm[threadIdx.x] += a;
        __syncthreads();
    }
    int base = g_part[blockIdx.x];
    if (t < N) {
        g_rowptr[t] = base + sm[threadIdx.x] - v;
        if (t == N - 1) g_rowptr[N] = base + sm[threadIdx.x];
    }
}

__global__ void csr_scatter(const int* __restrict__ ei, int E, int Et) {
    int i = blockIdx.x * blockDim.x + threadIdx.x;
    if (i >= Et) return;
    int s, d;
    if (i < E) { s = __ldg(&ei[i]); d = __ldg(&ei[E + i]); }
    else       { s = d = i - E; }
    int pos = __ldg(&g_rowptr[d]) + atomicAdd(&g_fill[d], 1);
    g_col[pos] = s;
}

// ---------------- fused GAT: online softmax + aggregate + epilogue -------------
// One warp per dst node; 2-way edge unroll with independent softmax states to
// break the loop-carried dependency (merged exactly at the end).
struct SmState { float m, s; float4 acc; };

__device__ __forceinline__ void sm_init(SmState& st) {
    st.m = -3.4e38f; st.s = 0.f;
    st.acc = make_float4(0.f, 0.f, 0.f, 0.f);
}
__device__ __forceinline__ void sm_update(SmState& st, float logit, float4 x) {
    float m2 = fmaxf(st.m, logit);
    float c  = __expf(st.m - m2);
    float p  = __expf(logit - m2);
    st.s = st.s * c + p; st.m = m2;
    st.acc.x = st.acc.x * c + p * x.x;
    st.acc.y = st.acc.y * c + p * x.y;
    st.acc.z = st.acc.z * c + p * x.z;
    st.acc.w = st.acc.w * c + p * x.w;
}
__device__ __forceinline__ void sm_merge(SmState& a, const SmState& b) {
    float m = fmaxf(a.m, b.m);
    float ca = __expf(a.m - m), cb = __expf(b.m - m);
    a.s = a.s * ca + b.s * cb; a.m = m;
    a.acc.x = a.acc.x * ca + b.acc.x * cb;
    a.acc.y = a.acc.y * ca + b.acc.y * cb;
    a.acc.z = a.acc.z * ca + b.acc.z * cb;
    a.acc.w = a.acc.w * ca + b.acc.w * cb;
}

__global__ __launch_bounds__(128) void fused_gat(
    const float* __restrict__ att, const float* __restrict__ bias,
    float* __restrict__ out, int N)
{
    int n    = (blockIdx.x * blockDim.x + threadIdx.x) >> 5;
    int lane = threadIdx.x & 31;
    if (n >= N) return;

    int l4 = lane * 4;
    float4 a0 = *(const float4*)&att[l4];          // head l/16, chans (l%16)*4
    float4 a1 = *(const float4*)&att[128 + l4];    // head 2+l/16

    const float* xdr = &g_xd[(size_t)n * HC];
    float4 d0 = *(const float4*)&xdr[l4];
    float4 d1 = *(const float4*)&xdr[128 + l4];

    int beg = __ldg(&g_rowptr[n]), end = __ldg(&g_rowptr[n + 1]);

    SmState A1, A2, B1, B2;
    sm_init(A1); sm_init(A2); sm_init(B1); sm_init(B2);

    int e = beg;
    for (; e + 1 < end; e += 2) {
        int s0 = __ldg(&g_col[e]);
        int s1 = __ldg(&g_col[e + 1]);
        const float* xr0 = &g_xs[(size_t)s0 * HC];
        const float* xr1 = &g_xs[(size_t)s1 * HC];
        float4 u0 = *(const float4*)&xr0[l4];
        float4 u1 = *(const float4*)&xr0[128 + l4];
        float4 v0 = *(const float4*)&xr1[l4];
        float4 v1 = *(const float4*)&xr1[128 + l4];

        float pu0 = lrelu(u0.x + d0.x) * a0.x + lrelu(u0.y + d0.y) * a0.y
                  + lrelu(u0.z + d0.z) * a0.z + lrelu(u0.w + d0.w) * a0.w;
        float pu1 = lrelu(u1.x + d1.x) * a1.x + lrelu(u1.y + d1.y) * a1.y
                  + lrelu(u1.z + d1.z) * a1.z + lrelu(u1.w + d1.w) * a1.w;
        float pv0 = lrelu(v0.x + d0.x) * a0.x + lrelu(v0.y + d0.y) * a0.y
                  + lrelu(v0.z + d0.z) * a0.z + lrelu(v0.w + d0.w) * a0.w;
        float pv1 = lrelu(v1.x + d1.x) * a1.x + lrelu(v1.y + d1.y) * a1.y
                  + lrelu(v1.z + d1.z) * a1.z + lrelu(v1.w + d1.w) * a1.w;
#pragma unroll
        for (int off = 8; off >= 1; off >>= 1) {
            pu0 += __shfl_xor_sync(0xFFFFFFFFu, pu0, off);
            pu1 += __shfl_xor_sync(0xFFFFFFFFu, pu1, off);
            pv0 += __shfl_xor_sync(0xFFFFFFFFu, pv0, off);
            pv1 += __shfl_xor_sync(0xFFFFFFFFu, pv1, off);
        }
        sm_update(A1, pu0, u0);
        sm_update(B1, pu1, u1);
        sm_update(A2, pv0, v0);
        sm_update(B2, pv1, v1);
    }
    if (e < end) {
        int s0 = __ldg(&g_col[e]);
        const float* xr0 = &g_xs[(size_t)s0 * HC];
        float4 u0 = *(const float4*)&xr0[l4];
        float4 u1 = *(const float4*)&xr0[128 + l4];
        float pu0 = lrelu(u0.x + d0.x) * a0.x + lrelu(u0.y + d0.y) * a0.y
                  + lrelu(u0.z + d0.z) * a0.z + lrelu(u0.w + d0.w) * a0.w;
        float pu1 = lrelu(u1.x + d1.x) * a1.x + lrelu(u1.y + d1.y) * a1.y
                  + lrelu(u1.z + d1.z) * a1.z + lrelu(u1.w + d1.w) * a1.w;
#pragma unroll
        for (int off = 8; off >= 1; off >>= 1) {
            pu0 += __shfl_xor_sync(0xFFFFFFFFu, pu0, off);
            pu1 += __shfl_xor_sync(0xFFFFFFFFu, pu1, off);
        }
        sm_update(A1, pu0, u0);
        sm_update(B1, pu1, u1);
    }

    sm_merge(A1, A2);
    sm_merge(B1, B2);

    float iA = 1.f / A1.s, iB = 1.f / B1.s;
    float t0 = A1.acc.x * iA + B1.acc.x * iB;
    float t1 = A1.acc.y * iA + B1.acc.y * iB;
    float t2 = A1.acc.z * iA + B1.acc.z * iB;
    float t3 = A1.acc.w * iA + B1.acc.w * iB;
    t0 += __shfl_xor_sync(0xFFFFFFFFu, t0, 16);
    t1 += __shfl_xor_sync(0xFFFFFFFFu, t1, 16);
    t2 += __shfl_xor_sync(0xFFFFFFFFu, t2, 16);
    t3 += __shfl_xor_sync(0xFFFFFFFFu, t3, 16);

    if (lane < 16) {
        int c = lane * 4;
        float4 bv = *(const float4*)&bias[c];
        float4 o;
        o.x = 0.25f * t0 + bv.x; o.x = o.x > 0.f ? o.x : expm1f(o.x);
        o.y = 0.25f * t1 + bv.y; o.y = o.y > 0.f ? o.y : expm1f(o.y);
        o.z = 0.25f * t2 + bv.z; o.z = o.z > 0.f ? o.z : expm1f(o.z);
        o.w = 0.25f * t3 + bv.w; o.w = o.w > 0.f ? o.w : expm1f(o.w);
        *(float4*)&out[(size_t)n * HID + c] = o;
    }
}

// ---------------- launch -------------------------------------------------------
extern "C" void kernel_launch(void* const* d_in, const int* in_sizes, int n_in,
                              void* d_out, int out_size)
{
    const float* x  = (const float*)d_in[0];
    const int*   ei = (const int*)d_in[1];
    int wi = 3;
    if (n_in >= 12 && in_sizes[3] == 1) wi = 4;
    const float* gamma = (const float*)d_in[wi + 0];
    const float* beta  = (const float*)d_in[wi + 1];
    const float* wl    = (const float*)d_in[wi + 2];
    const float* bl    = (const float*)d_in[wi + 3];
    const float* wr    = (const float*)d_in[wi + 4];
    const float* br    = (const float*)d_in[wi + 5];
    const float* att   = (const float*)d_in[wi + 6];
    const float* bias  = (const float*)d_in[wi + 7];

    int N  = in_sizes[0] / F_IN;
    int E  = in_sizes[1] / 2;
    int Et = E + N;

    void *p_stats, *p_cnt, *p_fill;
    cudaGetSymbolAddress(&p_stats, g_stats);
    cudaGetSymbolAddress(&p_cnt,   g_cnt);
    cudaGetSymbolAddress(&p_fill,  g_fill);
    cudaMemsetAsync(p_stats, 0, (size_t)2 * F_IN * sizeof(float));
    cudaMemsetAsync(p_cnt,   0, (size_t)N * sizeof(int));
    cudaMemsetAsync(p_fill,  0, (size_t)N * sizeof(int));

    bn_stats<<<2048, 256>>>(x, N);
    bn_final<<<1, 128>>>(gamma, beta, N);

    dim3 g2(4, (N + 127) / 128);
    gemm_xsxd<<<g2, 256>>>(x, wl, bl, wr, br, N);

    csr_hist<<<(E + 255) / 256, 256>>>(ei, E);
    csr_scan1<<<256, 256>>>(N);
    csr_scan2<<<1, 256>>>();
    csr_scan3<<<256, 256>>>(N);
    csr_scatter<<<(Et + 255) / 256, 256>>>(ei, E, Et);

    fused_gat<<<(N * 32 + 127) / 128, 128>>>(att, bias, (float*)d_out, N);
}

// round 17
// speedup vs baseline: 1.8091x; 1.2860x over previous
#include <cuda_runtime.h>
#include <cuda_bf16.h>
#include <mma.h>

using namespace nvcuda;

#define MAXN 65536
#define MAXE 1048576
#define MAXET (MAXE + MAXN)
#define F_IN 128
#define HC 256     // HEADS*HID
#define HID 64
#define HEADS 4

// ---------------- scratch ------------------------------------------------------
__device__ float g_xs[(size_t)MAXN * HC];      // 64 MB
__device__ float g_xd[(size_t)MAXN * HC];      // 64 MB
__device__ int   g_cnt[MAXN];
__device__ int   g_fill[MAXN];
__device__ int   g_rowptr[MAXN + 1];
__device__ int   g_col[MAXET];
__device__ int   g_part[256];
__device__ float g_stats[4 * F_IN];            // [sum | sumsq | scale | shift]

__device__ __forceinline__ float lrelu(float v) {
    return fmaxf(v, 0.f) + 0.2f * fminf(v, 0.f);
}

// ---------------- K1: BN stats -------------------------------------------------
__global__ void bn_stats(const float* __restrict__ x, int N) {
    __shared__ float shs[256], shq[256];
    int col  = threadIdx.x & 127;
    int half = threadIdx.x >> 7;
    float s = 0.f, q = 0.f;
    for (int r = blockIdx.x * 2 + half; r < N; r += gridDim.x * 2) {
        float v = x[(size_t)r * F_IN + col];
        s += v; q += v * v;
    }
    shs[threadIdx.x] = s; shq[threadIdx.x] = q;
    __syncthreads();
    if (half == 0) {
        atomicAdd(&g_stats[col],        s + shs[threadIdx.x + 128]);
        atomicAdd(&g_stats[F_IN + col], q + shq[threadIdx.x + 128]);
    }
}

__global__ void bn_final(const float* __restrict__ gamma, const float* __restrict__ beta, int N) {
    int c = threadIdx.x;
    if (c >= F_IN) return;
    float inv_n = 1.f / (float)N;
    float mean = g_stats[c] * inv_n;
    float var  = g_stats[F_IN + c] * inv_n - mean * mean;
    float sc   = gamma[c] * rsqrtf(var + 1e-5f);
    g_stats[2 * F_IN + c] = sc;
    g_stats[3 * F_IN + c] = beta[c] - mean * sc;
}

// ---------------- K2: BN + dual GEMM via split-bf16 tensor-core MMA ------------
// out = xn @ W^T with xn, W each split into bf16 hi+lo; 3-term product
// (AhBh + AhBl + AlBh) accumulated in fp32 => ~1e-5 relative error.
// CTA tile 128 rows x 128 cols; 8 warps, each 64x32 (4x2 wmma 16x16x16 tiles).
#define KC 32                     // K chunk staged in smem
#define LDA 40                    // bf16 row stride (80B, mult of 16B)
#define STAGE_ELEMS (128 * LDA)   // per hi/lo per matrix

__global__ __launch_bounds__(256) void gemm_xsxd(
    const float* __restrict__ x,
    const float* __restrict__ wl, const float* __restrict__ bl,
    const float* __restrict__ wr, const float* __restrict__ br, int N)
{
    // 40960B staging (union'd with epilogue buffer) + scale/shift
    __shared__ __align__(16) unsigned char smbuf[4 * STAGE_ELEMS * 2];
    __shared__ float s_sc[F_IN], s_sf[F_IN];

    __nv_bfloat16* Ah = (__nv_bfloat16*)smbuf;
    __nv_bfloat16* Al = Ah + STAGE_ELEMS;
    __nv_bfloat16* Bh = Al + STAGE_ELEMS;
    __nv_bfloat16* Bl = Bh + STAGE_ELEMS;

    int tid  = threadIdx.x;
    int row0 = blockIdx.y * 128;
    int col0 = blockIdx.x * 128;            // in [0,512)
    bool isl = (col0 < HC);

    if (tid < F_IN) {
        s_sc[tid] = g_stats[2 * F_IN + tid];
        s_sf[tid] = g_stats[3 * F_IN + tid];
    }

    int w    = tid >> 5;
    int lane = tid & 31;
    int wr_  = w >> 2;        // 0..1  (64-row block)
    int wc   = w & 3;         // 0..3  (32-col block)

    wmma::fragment<wmma::accumulator, 16, 16, 16, float> acc[4][2];
#pragma unroll
    for (int i = 0; i < 4; i++)
#pragma unroll
        for (int j = 0; j < 2; j++) wmma::fill_fragment(acc[i][j], 0.f);

    for (int kc = 0; kc < F_IN / KC; kc++) {
        int k0 = kc * KC;
        __syncthreads();
        // stage A (BN applied + split) and B (split): 1024 float4 tasks each
#pragma unroll
        for (int t = 0; t < 4; t++) {
            int L = tid + t * 256;
            int r = L >> 3;           // row (A) / out-col (B)
            int q = L & 7;            // float4 within 32-k chunk
            // ---- A
            float4 v = *(const float4*)&x[(size_t)(row0 + r) * F_IN + k0 + q * 4];
            float f[4] = { v.x * s_sc[k0 + q * 4 + 0] + s_sf[k0 + q * 4 + 0],
                           v.y * s_sc[k0 + q * 4 + 1] + s_sf[k0 + q * 4 + 1],
                           v.z * s_sc[k0 + q * 4 + 2] + s_sf[k0 + q * 4 + 2],
                           v.w * s_sc[k0 + q * 4 + 3] + s_sf[k0 + q * 4 + 3] };
#pragma unroll
            for (int c = 0; c < 4; c++) {
                __nv_bfloat16 hi = __float2bfloat16(f[c]);
                __nv_bfloat16 lo = __float2bfloat16(f[c] - __bfloat162float(hi));
                Ah[r * LDA + q * 4 + c] = hi;
                Al[r * LDA + q * 4 + c] = lo;
            }
            // ---- B (row r of W side for out-col gc)
            int gc = col0 + r;
            const float* wsrc = isl ? &wl[(size_t)gc * F_IN]
                                    : &wr[(size_t)(gc - HC) * F_IN];
            float4 wv = *(const float4*)&wsrc[k0 + q * 4];
            float g[4] = { wv.x, wv.y, wv.z, wv.w };
#pragma unroll
            for (int c = 0; c < 4; c++) {
                __nv_bfloat16 hi = __float2bfloat16(g[c]);
                __nv_bfloat16 lo = __float2bfloat16(g[c] - __bfloat162float(hi));
                Bh[r * LDA + q * 4 + c] = hi;
                Bl[r * LDA + q * 4 + c] = lo;
            }
        }
        __syncthreads();

#pragma unroll
        for (int kk = 0; kk < KC / 16; kk++) {
            wmma::fragment<wmma::matrix_b, 16, 16, 16, __nv_bfloat16, wmma::col_major> bh[2], blo[2];
#pragma unroll
            for (int j = 0; j < 2; j++) {
                const __nv_bfloat16* bp = &Bh[(wc * 32 + j * 16) * LDA + kk * 16];
                const __nv_bfloat16* lp = &Bl[(wc * 32 + j * 16) * LDA + kk * 16];
                wmma::load_matrix_sync(bh[j],  bp, LDA);
                wmma::load_matrix_sync(blo[j], lp, LDA);
            }
#pragma unroll
            for (int i = 0; i < 4; i++) {
                wmma::fragment<wmma::matrix_a, 16, 16, 16, __nv_bfloat16, wmma::row_major> ah, alo;
                wmma::load_matrix_sync(ah,  &Ah[(wr_ * 64 + i * 16) * LDA + kk * 16], LDA);
                wmma::load_matrix_sync(alo, &Al[(wr_ * 64 + i * 16) * LDA + kk * 16], LDA);
#pragma unroll
                for (int j = 0; j < 2; j++) {
                    wmma::mma_sync(acc[i][j], alo, bh[j],  acc[i][j]);
                    wmma::mma_sync(acc[i][j], ah,  blo[j], acc[i][j]);
                    wmma::mma_sync(acc[i][j], ah,  bh[j],  acc[i][j]);
                }
            }
        }
    }

    // epilogue: per-warp smem round-trip (reuses staging buffer), add bias, store
    __syncthreads();
    float* ep = (float*)smbuf + w * (16 * 20);
    int r  = lane >> 1;
    int cs = (lane & 1) * 8;
#pragma unroll
    for (int i = 0; i < 4; i++) {
#pragma unroll
        for (int j = 0; j < 2; j++) {
            wmma::store_matrix_sync(ep, acc[i][j], 20, wmma::mem_row_major);
            __syncwarp();
            int gr   = row0 + wr_ * 64 + i * 16 + r;
            int gcol = col0 + wc * 32 + j * 16 + cs;
            float vals[8];
#pragma unroll
            for (int t = 0; t < 8; t++)
                vals[t] = ep[r * 20 + cs + t]
                        + (isl ? __ldg(&bl[gcol + t]) : __ldg(&br[gcol - HC + t]));
            float* dst = isl ? &g_xs[(size_t)gr * HC + gcol]
                             : &g_xd[(size_t)gr * HC + (gcol - HC)];
            *(float4*)(dst)     = make_float4(vals[0], vals[1], vals[2], vals[3]);
            *(float4*)(dst + 4) = make_float4(vals[4], vals[5], vals[6], vals[7]);
            __syncwarp();
        }
    }
}

// ---------------- CSR build ----------------------------------------------------
__global__ void csr_hist(const int* __restrict__ ei, int E) {
    int e = blockIdx.x * blockDim.x + threadIdx.x;
    if (e < E) atomicAdd(&g_cnt[__ldg(&ei[E + e])], 1);
}

__global__ void csr_scan1(int N) {
    __shared__ int sm[256];
    int t = blockIdx.x * 256 + threadIdx.x;
    sm[threadIdx.x] = (t < N) ? (g_cnt[t] + 1) : 0;
    __syncthreads();
#pragma unroll
    for (int off = 128; off > 0; off >>= 1) {
        if (threadIdx.x < off) sm[threadIdx.x] += sm[threadIdx.x + off];
        __syncthreads();
    }
    if (threadIdx.x == 0) g_part[blockIdx.x] = sm[0];
}

__global__ void csr_scan2() {
    __shared__ int sm[256];
    int v = g_part[threadIdx.x];
    sm[threadIdx.x] = v;
    __syncthreads();
    for (int off = 1; off < 256; off <<= 1) {
        int a = (threadIdx.x >= off) ? sm[threadIdx.x - off] : 0;
        __syncthreads();
        sm[threadIdx.x] += a;
        __syncthreads();
    }
    g_part[threadIdx.x] = sm[threadIdx.x] - v;   // exclusive
}

__global__ void csr_scan3(int N) {
    __shared__ int sm[256];
    int t = blockIdx.x * 256 + threadIdx.x;
    int v = (t < N) ? (g_cnt[t] + 1) : 0;
    sm[threadIdx.x] = v;
    __syncthreads();
    for (int off = 1; off < 256; off <<= 1) {
        int a = (threadIdx.x >= off) ? sm[threadIdx.x - off] : 0;
        __syncthreads();
        sm[threadIdx.x] += a;
        __syncthreads();
    }
    int base = g_part[blockIdx.x];
    if (t < N) {
        g_rowptr[t] = base + sm[threadIdx.x] - v;
        if (t == N - 1) g_rowptr[N] = base + sm[threadIdx.x];
    }
}

__global__ void csr_scatter(const int* __restrict__ ei, int E, int Et) {
    int i = blockIdx.x * blockDim.x + threadIdx.x;
    if (i >= Et) return;
    int s, d;
    if (i < E) { s = __ldg(&ei[i]); d = __ldg(&ei[E + i]); }
    else       { s = d = i - E; }
    int pos = __ldg(&g_rowptr[d]) + atomicAdd(&g_fill[d], 1);
    g_col[pos] = s;
}

// ---------------- fused GAT: online softmax + aggregate + epilogue -------------
struct SmState { float m, s; float4 acc; };

__device__ __forceinline__ void sm_init(SmState& st) {
    st.m = -3.4e38f; st.s = 0.f;
    st.acc = make_float4(0.f, 0.f, 0.f, 0.f);
}
__device__ __forceinline__ void sm_update(SmState& st, float logit, float4 x) {
    float m2 = fmaxf(st.m, logit);
    float c  = __expf(st.m - m2);
    float p  = __expf(logit - m2);
    st.s = st.s * c + p; st.m = m2;
    st.acc.x = st.acc.x * c + p * x.x;
    st.acc.y = st.acc.y * c + p * x.y;
    st.acc.z = st.acc.z * c + p * x.z;
    st.acc.w = st.acc.w * c + p * x.w;
}
__device__ __forceinline__ void sm_merge(SmState& a, const SmState& b) {
    float m = fmaxf(a.m, b.m);
    float ca = __expf(a.m - m), cb = __expf(b.m - m);
    a.s = a.s * ca + b.s * cb; a.m = m;
    a.acc.x = a.acc.x * ca + b.acc.x * cb;
    a.acc.y = a.acc.y * ca + b.acc.y * cb;
    a.acc.z = a.acc.z * ca + b.acc.z * cb;
    a.acc.w = a.acc.w * ca + b.acc.w * cb;
}

__global__ __launch_bounds__(128) void fused_gat(
    const float* __restrict__ att, const float* __restrict__ bias,
    float* __restrict__ out, int N)
{
    int n    = (blockIdx.x * blockDim.x + threadIdx.x) >> 5;
    int lane = threadIdx.x & 31;
    if (n >= N) return;

    int l4 = lane * 4;
    float4 a0 = *(const float4*)&att[l4];
    float4 a1 = *(const float4*)&att[128 + l4];

    const float* xdr = &g_xd[(size_t)n * HC];
    float4 d0 = *(const float4*)&xdr[l4];
    float4 d1 = *(const float4*)&xdr[128 + l4];

    int beg = __ldg(&g_rowptr[n]), end = __ldg(&g_rowptr[n + 1]);

    SmState A1, A2, B1, B2;
    sm_init(A1); sm_init(A2); sm_init(B1); sm_init(B2);

    int e = beg;
    for (; e + 1 < end; e += 2) {
        int s0 = __ldg(&g_col[e]);
        int s1 = __ldg(&g_col[e + 1]);
        const float* xr0 = &g_xs[(size_t)s0 * HC];
        const float* xr1 = &g_xs[(size_t)s1 * HC];
        float4 u0 = *(const float4*)&xr0[l4];
        float4 u1 = *(const float4*)&xr0[128 + l4];
        float4 v0 = *(const float4*)&xr1[l4];
        float4 v1 = *(const float4*)&xr1[128 + l4];

        float pu0 = lrelu(u0.x + d0.x) * a0.x + lrelu(u0.y + d0.y) * a0.y
                  + lrelu(u0.z + d0.z) * a0.z + lrelu(u0.w + d0.w) * a0.w;
        float pu1 = lrelu(u1.x + d1.x) * a1.x + lrelu(u1.y + d1.y) * a1.y
                  + lrelu(u1.z + d1.z) * a1.z + lrelu(u1.w + d1.w) * a1.w;
        float pv0 = lrelu(v0.x + d0.x) * a0.x + lrelu(v0.y + d0.y) * a0.y
                  + lrelu(v0.z + d0.z) * a0.z + lrelu(v0.w + d0.w) * a0.w;
        float pv1 = lrelu(v1.x + d1.x) * a1.x + lrelu(v1.y + d1.y) * a1.y
                  + lrelu(v1.z + d1.z) * a1.z + lrelu(v1.w + d1.w) * a1.w;
#pragma unroll
        for (int off = 8; off >= 1; off >>= 1) {
            pu0 += __shfl_xor_sync(0xFFFFFFFFu, pu0, off);
            pu1 += __shfl_xor_sync(0xFFFFFFFFu, pu1, off);
            pv0 += __shfl_xor_sync(0xFFFFFFFFu, pv0, off);
            pv1 += __shfl_xor_sync(0xFFFFFFFFu, pv1, off);
        }
        sm_update(A1, pu0, u0);
        sm_update(B1, pu1, u1);
        sm_update(A2, pv0, v0);
        sm_update(B2, pv1, v1);
    }
    if (e < end) {
        int s0 = __ldg(&g_col[e]);
        const float* xr0 = &g_xs[(size_t)s0 * HC];
        float4 u0 = *(const float4*)&xr0[l4];
        float4 u1 = *(const float4*)&xr0[128 + l4];
        float pu0 = lrelu(u0.x + d0.x) * a0.x + lrelu(u0.y + d0.y) * a0.y
                  + lrelu(u0.z + d0.z) * a0.z + lrelu(u0.w + d0.w) * a0.w;
        float pu1 = lrelu(u1.x + d1.x) * a1.x + lrelu(u1.y + d1.y) * a1.y
                  + lrelu(u1.z + d1.z) * a1.z + lrelu(u1.w + d1.w) * a1.w;
#pragma unroll
        for (int off = 8; off >= 1; off >>= 1) {
            pu0 += __shfl_xor_sync(0xFFFFFFFFu, pu0, off);
            pu1 += __shfl_xor_sync(0xFFFFFFFFu, pu1, off);
        }
        sm_update(A1, pu0, u0);
        sm_update(B1, pu1, u1);
    }

    sm_merge(A1, A2);
    sm_merge(B1, B2);

    float iA = 1.f / A1.s, iB = 1.f / B1.s;
    float t0 = A1.acc.x * iA + B1.acc.x * iB;
    float t1 = A1.acc.y * iA + B1.acc.y * iB;
    float t2 = A1.acc.z * iA + B1.acc.z * iB;
    float t3 = A1.acc.w * iA + B1.acc.w * iB;
    t0 += __shfl_xor_sync(0xFFFFFFFFu, t0, 16);
    t1 += __shfl_xor_sync(0xFFFFFFFFu, t1, 16);
    t2 += __shfl_xor_sync(0xFFFFFFFFu, t2, 16);
    t3 += __shfl_xor_sync(0xFFFFFFFFu, t3, 16);

    if (lane < 16) {
        int c = lane * 4;
        float4 bv = *(const float4*)&bias[c];
        float4 o;
        o.x = 0.25f * t0 + bv.x; o.x = o.x > 0.f ? o.x : expm1f(o.x);
        o.y = 0.25f * t1 + bv.y; o.y = o.y > 0.f ? o.y : expm1f(o.y);
        o.z = 0.25f * t2 + bv.z; o.z = o.z > 0.f ? o.z : expm1f(o.z);
        o.w = 0.25f * t3 + bv.w; o.w = o.w > 0.f ? o.w : expm1f(o.w);
        *(float4*)&out[(size_t)n * HID + c] = o;
    }
}

// ---------------- launch -------------------------------------------------------
extern "C" void kernel_launch(void* const* d_in, const int* in_sizes, int n_in,
                              void* d_out, int out_size)
{
    const float* x  = (const float*)d_in[0];
    const int*   ei = (const int*)d_in[1];
    int wi = 3;
    if (n_in >= 12 && in_sizes[3] == 1) wi = 4;
    const float* gamma = (const float*)d_in[wi + 0];
    const float* beta  = (const float*)d_in[wi + 1];
    const float* wl    = (const float*)d_in[wi + 2];
    const float* bl    = (const float*)d_in[wi + 3];
    const float* wr    = (const float*)d_in[wi + 4];
    const float* br    = (const float*)d_in[wi + 5];
    const float* att   = (const float*)d_in[wi + 6];
    const float* bias  = (const float*)d_in[wi + 7];

    int N  = in_sizes[0] / F_IN;
    int E  = in_sizes[1] / 2;
    int Et = E + N;

    void *p_stats, *p_cnt, *p_fill;
    cudaGetSymbolAddress(&p_stats, g_stats);
    cudaGetSymbolAddress(&p_cnt,   g_cnt);
    cudaGetSymbolAddress(&p_fill,  g_fill);
    cudaMemsetAsync(p_stats, 0, (size_t)2 * F_IN * sizeof(float));
    cudaMemsetAsync(p_cnt,   0, (size_t)N * sizeof(int));
    cudaMemsetAsync(p_fill,  0, (size_t)N * sizeof(int));

    bn_stats<<<2048, 256>>>(x, N);
    bn_final<<<1, 128>>>(gamma, beta, N);

    dim3 g2(4, (N + 127) / 128);
    gemm_xsxd<<<g2, 256>>>(x, wl, bl, wr, br, N);

    csr_hist<<<(E + 255) / 256, 256>>>(ei, E);
    csr_scan1<<<256, 256>>>(N);
    csr_scan2<<<1, 256>>>();
    csr_scan3<<<256, 256>>>(N);
    csr_scatter<<<(Et + 255) / 256, 256>>>(ei, E, Et);

    fused_gat<<<(N * 32 + 127) / 128, 128>>>(att, bias, (float*)d_out, N);
}